// round 7
// baseline (speedup 1.0000x reference)
#include <cuda_runtime.h>
#include <cuda_fp16.h>
#include <cstdint>

#define N_ATOMS 8000
#define N_PAIRS 80000
#define NF 32
#define GN_EPS 1e-5f

#define NB 592            // 4 CTAs/SM x 148 SMs: all resident in wave 1
#define NT 256

// Scratch (device globals: no allocation allowed)
// A-table fp16 packed: A2[a*256 + q*32 + o] = half2( A[a,2q,o], A[a,2q+1,o] )
__device__ __align__(16) uint32_t g_A2[(size_t)N_ATOMS * 256];
// transposed fp16 weights: WT2[f*256 + q*32 + o] = half2(W[2q,o,f], W[2q+1,o,f])
__device__ __align__(16) uint32_t g_WT2[32 * 256];
// sense table fp32: sense[p*16 + d] = cut(d_p) * exp(...)
__device__ __align__(16) float g_sense[(size_t)N_PAIRS * 16];
__device__ __align__(16) float g_self[(size_t)N_ATOMS * NF];
__device__ int g_seg[N_ATOMS + 1];
__device__ int g_ctrB;                 // dynamic atom counter for phase B

// Grid barrier state: monotonic across launches (deterministic, no reset).
__device__ unsigned long long g_arrive = 0;
__device__ volatile unsigned long long g_release = 0;

__device__ __forceinline__ void grid_barrier() {
    __syncthreads();
    if (threadIdx.x == 0) {
        __threadfence();
        unsigned long long t = atomicAdd(&g_arrive, 1ULL) + 1ULL;
        unsigned long long target = ((t + NB - 1) / NB) * NB;
        if (t == target) {
            g_release = target;
        } else {
            int ns = 64;
            while (g_release < target) {
                __nanosleep(ns);
                if (ns < 4096) ns <<= 1;     // backoff: cut spin pollution
            }
        }
        __threadfence();
    }
    __syncthreads();
}

__device__ __forceinline__ float warp_sum(float v) {
#pragma unroll
    for (int off = 16; off; off >>= 1)
        v += __shfl_xor_sync(0xffffffffu, v, off);
    return v;
}

__device__ __forceinline__ void loadA(uint32_t A[8], int j, int lane) {
    const uint32_t* base = g_A2 + (size_t)j * 256 + lane;
#pragma unroll
    for (int q = 0; q < 8; ++q) A[q] = __ldg(base + q * 32);
}

__global__ void __launch_bounds__(NT, 4) k_fused(
    const float* __restrict__ feat,     // (N,32)
    const float* __restrict__ rhats,    // (P,4)
    const float* __restrict__ dist,     // (P,)
    const float* __restrict__ Wint,     // (16,32,32) d,o,f
    const float* __restrict__ sw,       // (32,32) o,f
    const float* __restrict__ sb,       // (32,)
    const float* __restrict__ mw,       // (64,32)
    const float* __restrict__ gnw,      // (64,)
    const float* __restrict__ gnb,      // (64,)
    const float* __restrict__ mu,       // (16,)
    const float* __restrict__ sg,       // (16,)
    const int*   __restrict__ pf,       // (P,)  sorted
    const int*   __restrict__ psec,     // (P,)
    float* __restrict__ out)            // (N,32)
{
    __shared__ __align__(16) float swT[NF * NF];   // transposed selfint weights
    __shared__ __align__(16) float fsh[4 * NF];    // feat staging for A3 tiles

    const int tid  = threadIdx.x;
    const int bid  = blockIdx.x;
    const int lane = tid & 31;
    const int wid  = tid >> 5;
    const int gtid = bid * NT + tid;

    // ============================ PHASE A0 ==================================
    if (gtid == 0) g_ctrB = 0;          // reset dynamic counter (barrier-ordered)

    // A0a: segment starts via scatter on sorted pair_first
    for (int p = gtid; p < N_PAIRS; p += NB * NT) {
        int cur  = pf[p];
        int prev = (p == 0) ? -1 : pf[p - 1];
        for (int a = prev + 1; a <= cur; ++a) g_seg[a] = p;
        if (p == N_PAIRS - 1)
            for (int a = cur + 1; a <= N_ATOMS; ++a) g_seg[a] = N_PAIRS;
    }

    // A0b: sense table
    for (int p = gtid; p < N_PAIRS; p += NB * NT) {
        const float dd = dist[p];
        const float invd = 1.0f / dd;
        float cut = 0.f;
        if (dd < 6.5f) {
            float cc = cospif(dd * (0.5f / 6.5f));
            cut = cc * cc;
        }
        float* sp = g_sense + (size_t)p * 16;
#pragma unroll
        for (int d = 0; d < 16; ++d) {
            float t = (invd - __ldg(mu + d)) / __ldg(sg + d);
            sp[d] = cut * __expf(-0.5f * t * t);
        }
    }

    // A0c: one block builds the transposed fp16 weight table
    if (bid == NB - 1) {
        for (int idx = tid; idx < 32 * 256; idx += NT) {
            int f = idx >> 8, rem = idx & 255;
            int q = rem >> 5, o = rem & 31;
            float a = Wint[(2 * q) * (NF * NF) + o * NF + f];
            float b = Wint[(2 * q + 1) * (NF * NF) + o * NF + f];
            __half2 h2 = __floats2half2_rn(a, b);
            g_WT2[idx] = *reinterpret_cast<uint32_t*>(&h2);
        }
    }

    // A0d: self-interaction (fp32)
    for (int i = tid; i < NF * NF; i += NT) {
        int o = i >> 5, f = i & 31;
        swT[f * NF + o] = sw[i];
    }
    __syncthreads();
    for (int idx = gtid; idx < N_ATOMS * NF; idx += NB * NT) {
        int a = idx >> 5, o = idx & 31;
        float s = sb[o];
        const float* fr = feat + (size_t)a * NF;
#pragma unroll
        for (int f = 0; f < NF; ++f)
            s = fmaf(fr[f], swT[f * NF + o], s);
        g_self[idx] = s;
    }

    grid_barrier();

    // ============================ PHASE A3 ==================================
    // A-table GEMM; 4-atom tiles (8 accumulator regs) to stay under 64 regs
    {
        const int c = wid * 32 + lane;
        const float4* fsh4 = (const float4*)fsh;
        for (int tile = bid; tile < N_ATOMS / 4; tile += NB) {
            const int a0 = tile * 4;
            __syncthreads();
            if (tid < 4 * NF) fsh[tid] = feat[(size_t)a0 * NF + tid];
            __syncthreads();
            float accA[4], accB[4];
#pragma unroll
            for (int k = 0; k < 4; ++k) { accA[k] = 0.f; accB[k] = 0.f; }
#pragma unroll
            for (int f4 = 0; f4 < 8; ++f4) {
                float2 wf[4];
#pragma unroll
                for (int t = 0; t < 4; ++t) {
                    uint32_t w2 = g_WT2[(4 * f4 + t) * 256 + c];
                    wf[t] = __half22float2(*reinterpret_cast<__half2*>(&w2));
                }
#pragma unroll
                for (int k = 0; k < 4; ++k) {
                    float4 v = fsh4[k * 8 + f4];
                    accA[k] = fmaf(v.x, wf[0].x, accA[k]);
                    accB[k] = fmaf(v.x, wf[0].y, accB[k]);
                    accA[k] = fmaf(v.y, wf[1].x, accA[k]);
                    accB[k] = fmaf(v.y, wf[1].y, accB[k]);
                    accA[k] = fmaf(v.z, wf[2].x, accA[k]);
                    accB[k] = fmaf(v.z, wf[2].y, accB[k]);
                    accA[k] = fmaf(v.w, wf[3].x, accA[k]);
                    accB[k] = fmaf(v.w, wf[3].y, accB[k]);
                }
            }
#pragma unroll
            for (int k = 0; k < 4; ++k) {
                __half2 h2 = __floats2half2_rn(accA[k], accB[k]);
                g_A2[(size_t)(a0 + k) * 256 + c] =
                    *reinterpret_cast<uint32_t*>(&h2);
            }
        }
    }

    grid_barrier();

    // ============================ PHASE B ===================================
    // dynamic warp-per-atom; lane = output channel o; even/odd double buffer
    int a;
    if (lane == 0) a = atomicAdd(&g_ctrB, 1);
    a = __shfl_sync(0xffffffffu, a, 0);

    while (a < N_ATOMS) {
        int an;
        if (lane == 0) an = atomicAdd(&g_ctrB, 1);   // grab next atom early

        const int p0 = g_seg[a];
        const int n  = g_seg[a + 1] - p0;

        float acc0 = 0.f, acc1 = 0.f, acc2 = 0.f, acc3 = 0.f;

        auto process_pair = [&](const uint32_t (&B)[8], int p) {
            const float4* sp = (const float4*)(g_sense + 16 * (size_t)p);
            const float4 rh = *(const float4*)(rhats + 4 * (size_t)p);
            float dA = 0.f, dB = 0.f;
#pragma unroll
            for (int g = 0; g < 4; ++g) {
                float4 s = sp[g];
                float2 a0v = __half22float2(*(const __half2*)(&B[2 * g]));
                float2 a1v = __half22float2(*(const __half2*)(&B[2 * g + 1]));
                dA = fmaf(s.x, a0v.x, dA);
                dB = fmaf(s.y, a0v.y, dB);
                dA = fmaf(s.z, a1v.x, dA);
                dB = fmaf(s.w, a1v.y, dB);
            }
            const float wgt = dA + dB;
            acc0 = fmaf(rh.x, wgt, acc0);
            acc1 = fmaf(rh.y, wgt, acc1);
            acc2 = fmaf(rh.z, wgt, acc2);
            acc3 = fmaf(rh.w, wgt, acc3);
        };

        if (n > 0) {
            uint32_t b0[8], b1[8];
            loadA(b0, psec[p0], lane);
            if (n > 1) loadA(b1, psec[p0 + 1], lane);
            int i = 0;
            for (;;) {
                process_pair(b0, p0 + i);
                if (i + 2 < n) loadA(b0, psec[p0 + i + 2], lane);
                if (++i >= n) break;
                process_pair(b1, p0 + i);
                if (i + 2 < n) loadA(b1, psec[p0 + i + 2], lane);
                if (++i >= n) break;
            }
        }

        // invariants
        const float inv0 = acc0;
        const float inv1 = acc1 * acc1 + acc2 * acc2 + acc3 * acc3;

        // GroupNorm over 32 lanes per group
        const float m0 = warp_sum(inv0) * (1.f / 32.f);
        const float m1 = warp_sum(inv1) * (1.f / 32.f);
        const float c0 = inv0 - m0;
        const float c1 = inv1 - m1;
        const float v0s = warp_sum(c0 * c0) * (1.f / 32.f);
        const float v1s = warp_sum(c1 * c1) * (1.f / 32.f);
        float xn0 = c0 * rsqrtf(v0s + GN_EPS);
        float xn1 = c1 * rsqrtf(v1s + GN_EPS);
        xn0 = fmaf(xn0, gnw[lane], gnb[lane]);
        xn1 = fmaf(xn1, gnw[32 + lane], gnb[32 + lane]);

        // mixing + self
        float oa = g_self[(size_t)a * NF + lane];
        float ob = 0.f;
#pragma unroll
        for (int oin = 0; oin < 32; ++oin) {
            const float n0 = __shfl_sync(0xffffffffu, xn0, oin);
            const float n1 = __shfl_sync(0xffffffffu, xn1, oin);
            oa = fmaf(n0, mw[(oin * 2 + 0) * NF + lane], oa);
            ob = fmaf(n1, mw[(oin * 2 + 1) * NF + lane], ob);
        }
        out[(size_t)a * NF + lane] = oa + ob;

        a = __shfl_sync(0xffffffffu, an, 0);
    }
}

// ---------------------------------------------------------------------------
extern "C" void kernel_launch(void* const* d_in, const int* in_sizes, int n_in,
                              void* d_out, int out_size) {
    const float* in_features = (const float*)d_in[0];
    const float* tensor_rhats = (const float*)d_in[1];
    const float* dist_pairs = (const float*)d_in[2];
    const float* int_weights = (const float*)d_in[3];
    const float* selfint_w = (const float*)d_in[4];
    const float* selfint_b = (const float*)d_in[5];
    const float* mixing_weights = (const float*)d_in[6];
    const float* gn_weight = (const float*)d_in[7];
    const float* gn_bias = (const float*)d_in[8];
    const float* sens_mu = (const float*)d_in[9];
    const float* sens_sigma = (const float*)d_in[10];
    const int* pair_first = (const int*)d_in[11];
    const int* pair_second = (const int*)d_in[12];
    float* out = (float*)d_out;

    k_fused<<<NB, NT>>>(in_features, tensor_rhats, dist_pairs, int_weights,
                        selfint_w, selfint_b, mixing_weights, gn_weight,
                        gn_bias, sens_mu, sens_sigma, pair_first, pair_second,
                        out);
}

// round 8
// speedup vs baseline: 1.0005x; 1.0005x over previous
#include <cuda_runtime.h>
#include <cuda_fp16.h>
#include <cstdint>

#define N_ATOMS 8000
#define N_PAIRS 80000
#define NF 32
#define GN_EPS 1e-5f

#define NB 500            // 4 CTAs/SM: 500 <= 592 capacity, all resident
#define NT 256
#define NWARPS (NB * 8)   // 4000 warps -> exactly 2 atoms per warp

// Scratch (device globals: no allocation allowed)
// A-table fp16 packed: A2[a*256 + q*32 + o] = half2( A[a,2q,o], A[a,2q+1,o] )
__device__ __align__(16) uint32_t g_A2[(size_t)N_ATOMS * 256];
// transposed fp16 weights: WT2[f*256 + q*32 + o] = half2(W[2q,o,f], W[2q+1,o,f])
__device__ __align__(16) uint32_t g_WT2[32 * 256];
// sense table fp32: sense[p*16 + d] = cut(d_p) * exp(...)
__device__ __align__(16) float g_sense[(size_t)N_PAIRS * 16];
__device__ __align__(16) float g_self[(size_t)N_ATOMS * NF];
__device__ int g_seg[N_ATOMS + 1];

// Grid barrier state: monotonic across launches (deterministic, no reset).
__device__ unsigned long long g_arrive = 0;
__device__ volatile unsigned long long g_release = 0;

__device__ __forceinline__ void grid_barrier() {
    __syncthreads();
    if (threadIdx.x == 0) {
        __threadfence();
        unsigned long long t = atomicAdd(&g_arrive, 1ULL) + 1ULL;
        unsigned long long target = ((t + NB - 1) / NB) * NB;
        if (t == target) {
            g_release = target;
        } else {
            int ns = 64;
            while (g_release < target) {
                __nanosleep(ns);
                if (ns < 4096) ns <<= 1;
            }
        }
        __threadfence();
    }
    __syncthreads();
}

__device__ __forceinline__ float warp_sum(float v) {
#pragma unroll
    for (int off = 16; off; off >>= 1)
        v += __shfl_xor_sync(0xffffffffu, v, off);
    return v;
}

__device__ __forceinline__ void loadA(uint32_t A[8], int j, int lane) {
    const uint32_t* base = g_A2 + (size_t)j * 256 + lane;
#pragma unroll
    for (int q = 0; q < 8; ++q) A[q] = __ldg(base + q * 32);
}

__global__ void __launch_bounds__(NT, 4) k_fused(
    const float* __restrict__ feat,     // (N,32)
    const float* __restrict__ rhats,    // (P,4)
    const float* __restrict__ dist,     // (P,)
    const float* __restrict__ Wint,     // (16,32,32) d,o,f
    const float* __restrict__ sw,       // (32,32) o,f
    const float* __restrict__ sb,       // (32,)
    const float* __restrict__ mw,       // (64,32)
    const float* __restrict__ gnw,      // (64,)
    const float* __restrict__ gnb,      // (64,)
    const float* __restrict__ mu,       // (16,)
    const float* __restrict__ sg,       // (16,)
    const int*   __restrict__ pf,       // (P,)  sorted
    const int*   __restrict__ psec,     // (P,)
    float* __restrict__ out)            // (N,32)
{
    __shared__ __align__(16) float swT[NF * NF];   // transposed selfint weights
    __shared__ __align__(16) float fsh[4 * NF];    // feat staging for A3 tiles

    const int tid  = threadIdx.x;
    const int bid  = blockIdx.x;
    const int lane = tid & 31;
    const int wid  = tid >> 5;
    const int gtid  = bid * NT + tid;
    const int gwarp = bid * 8 + wid;

    // per-lane sensitivity constants (d = lane & 15)
    const float mu_l  = mu[lane & 15];
    const float isg_l = 1.0f / sg[lane & 15];

    // ============================ PHASE A0 ==================================
    // A0a: segment starts via scatter on sorted pair_first
    for (int p = gtid; p < N_PAIRS; p += NB * NT) {
        int cur  = pf[p];
        int prev = (p == 0) ? -1 : pf[p - 1];
        for (int a = prev + 1; a <= cur; ++a) g_seg[a] = p;
        if (p == N_PAIRS - 1)
            for (int a = cur + 1; a <= N_ATOMS; ++a) g_seg[a] = N_PAIRS;
    }

    // A0b: sense table, warp-cooperative. lane = h*16 + d handles pair pb+h.
    // Store addr = (pb+h)*16 + d = pb*16 + lane -> one 128B wavefront / 2 pairs.
    {
        const int h = lane >> 4;                    // which of the 2 pairs
        for (int pb = gwarp * 2; pb < N_PAIRS; pb += NWARPS * 2) {
            const float dd = dist[pb + h];
            const float invd = 1.0f / dd;
            float cut = 0.f;
            if (dd < 6.5f) {
                float cc = cospif(dd * (0.5f / 6.5f));
                cut = cc * cc;
            }
            float t = (invd - mu_l) * isg_l;
            g_sense[(size_t)pb * 16 + lane] = cut * __expf(-0.5f * t * t);
        }
    }

    // A0c: one block builds the transposed fp16 weight table
    if (bid == NB - 1) {
        for (int idx = tid; idx < 32 * 256; idx += NT) {
            int f = idx >> 8, rem = idx & 255;
            int q = rem >> 5, o = rem & 31;
            float a = Wint[(2 * q) * (NF * NF) + o * NF + f];
            float b = Wint[(2 * q + 1) * (NF * NF) + o * NF + f];
            __half2 h2 = __floats2half2_rn(a, b);
            g_WT2[idx] = *reinterpret_cast<uint32_t*>(&h2);
        }
    }

    // A0d: self-interaction (fp32)
    for (int i = tid; i < NF * NF; i += NT) {
        int o = i >> 5, f = i & 31;
        swT[f * NF + o] = sw[i];
    }
    __syncthreads();
    for (int idx = gtid; idx < N_ATOMS * NF; idx += NB * NT) {
        int a = idx >> 5, o = idx & 31;
        float s = sb[o];
        const float* fr = feat + (size_t)a * NF;
#pragma unroll
        for (int f = 0; f < NF; ++f)
            s = fmaf(fr[f], swT[f * NF + o], s);
        g_self[idx] = s;
    }

    grid_barrier();

    // ============================ PHASE A3 ==================================
    // A-table GEMM; 4-atom tiles (8 accumulator regs), weights coalesced
    {
        const int c = wid * 32 + lane;
        const float4* fsh4 = (const float4*)fsh;
        for (int tile = bid; tile < N_ATOMS / 4; tile += NB) {
            const int a0 = tile * 4;
            __syncthreads();
            if (tid < 4 * NF) fsh[tid] = feat[(size_t)a0 * NF + tid];
            __syncthreads();
            float accA[4], accB[4];
#pragma unroll
            for (int k = 0; k < 4; ++k) { accA[k] = 0.f; accB[k] = 0.f; }
#pragma unroll
            for (int f4 = 0; f4 < 8; ++f4) {
                float2 wf[4];
#pragma unroll
                for (int t = 0; t < 4; ++t) {
                    uint32_t w2 = g_WT2[(4 * f4 + t) * 256 + c];
                    wf[t] = __half22float2(*reinterpret_cast<__half2*>(&w2));
                }
#pragma unroll
                for (int k = 0; k < 4; ++k) {
                    float4 v = fsh4[k * 8 + f4];
                    accA[k] = fmaf(v.x, wf[0].x, accA[k]);
                    accB[k] = fmaf(v.x, wf[0].y, accB[k]);
                    accA[k] = fmaf(v.y, wf[1].x, accA[k]);
                    accB[k] = fmaf(v.y, wf[1].y, accB[k]);
                    accA[k] = fmaf(v.z, wf[2].x, accA[k]);
                    accB[k] = fmaf(v.z, wf[2].y, accB[k]);
                    accA[k] = fmaf(v.w, wf[3].x, accA[k]);
                    accB[k] = fmaf(v.w, wf[3].y, accB[k]);
                }
            }
#pragma unroll
            for (int k = 0; k < 4; ++k) {
                __half2 h2 = __floats2half2_rn(accA[k], accB[k]);
                g_A2[(size_t)(a0 + k) * 256 + c] =
                    *reinterpret_cast<uint32_t*>(&h2);
            }
        }
    }

    grid_barrier();

    // ============================ PHASE B ===================================
    // static warp-per-atom, exactly 2 atoms per warp (perfect balance)
    for (int a = gwarp; a < N_ATOMS; a += NWARPS) {
        const int p0 = g_seg[a];
        const int n  = g_seg[a + 1] - p0;

        float acc0 = 0.f, acc1 = 0.f, acc2 = 0.f, acc3 = 0.f;

        auto process_pair = [&](const uint32_t (&B)[8], int p) {
            const float4* sp = (const float4*)(g_sense + 16 * (size_t)p);
            const float4 rh = *(const float4*)(rhats + 4 * (size_t)p);
            float dA = 0.f, dB = 0.f;
#pragma unroll
            for (int g = 0; g < 4; ++g) {
                float4 s = sp[g];
                float2 a0v = __half22float2(*(const __half2*)(&B[2 * g]));
                float2 a1v = __half22float2(*(const __half2*)(&B[2 * g + 1]));
                dA = fmaf(s.x, a0v.x, dA);
                dB = fmaf(s.y, a0v.y, dB);
                dA = fmaf(s.z, a1v.x, dA);
                dB = fmaf(s.w, a1v.y, dB);
            }
            const float wgt = dA + dB;
            acc0 = fmaf(rh.x, wgt, acc0);
            acc1 = fmaf(rh.y, wgt, acc1);
            acc2 = fmaf(rh.z, wgt, acc2);
            acc3 = fmaf(rh.w, wgt, acc3);
        };

        if (n > 0) {
            uint32_t b0[8], b1[8];
            loadA(b0, psec[p0], lane);
            if (n > 1) loadA(b1, psec[p0 + 1], lane);
            int i = 0;
            for (;;) {
                process_pair(b0, p0 + i);
                if (i + 2 < n) loadA(b0, psec[p0 + i + 2], lane);
                if (++i >= n) break;
                process_pair(b1, p0 + i);
                if (i + 2 < n) loadA(b1, psec[p0 + i + 2], lane);
                if (++i >= n) break;
            }
        }

        // invariants
        const float inv0 = acc0;
        const float inv1 = acc1 * acc1 + acc2 * acc2 + acc3 * acc3;

        // GroupNorm over 32 lanes per group
        const float m0 = warp_sum(inv0) * (1.f / 32.f);
        const float m1 = warp_sum(inv1) * (1.f / 32.f);
        const float c0 = inv0 - m0;
        const float c1 = inv1 - m1;
        const float v0s = warp_sum(c0 * c0) * (1.f / 32.f);
        const float v1s = warp_sum(c1 * c1) * (1.f / 32.f);
        float xn0 = c0 * rsqrtf(v0s + GN_EPS);
        float xn1 = c1 * rsqrtf(v1s + GN_EPS);
        xn0 = fmaf(xn0, gnw[lane], gnb[lane]);
        xn1 = fmaf(xn1, gnw[32 + lane], gnb[32 + lane]);

        // mixing + self
        float oa = g_self[(size_t)a * NF + lane];
        float ob = 0.f;
#pragma unroll
        for (int oin = 0; oin < 32; ++oin) {
            const float n0 = __shfl_sync(0xffffffffu, xn0, oin);
            const float n1 = __shfl_sync(0xffffffffu, xn1, oin);
            oa = fmaf(n0, mw[(oin * 2 + 0) * NF + lane], oa);
            ob = fmaf(n1, mw[(oin * 2 + 1) * NF + lane], ob);
        }
        out[(size_t)a * NF + lane] = oa + ob;
    }
}

// ---------------------------------------------------------------------------
extern "C" void kernel_launch(void* const* d_in, const int* in_sizes, int n_in,
                              void* d_out, int out_size) {
    const float* in_features = (const float*)d_in[0];
    const float* tensor_rhats = (const float*)d_in[1];
    const float* dist_pairs = (const float*)d_in[2];
    const float* int_weights = (const float*)d_in[3];
    const float* selfint_w = (const float*)d_in[4];
    const float* selfint_b = (const float*)d_in[5];
    const float* mixing_weights = (const float*)d_in[6];
    const float* gn_weight = (const float*)d_in[7];
    const float* gn_bias = (const float*)d_in[8];
    const float* sens_mu = (const float*)d_in[9];
    const float* sens_sigma = (const float*)d_in[10];
    const int* pair_first = (const int*)d_in[11];
    const int* pair_second = (const int*)d_in[12];
    float* out = (float*)d_out;

    k_fused<<<NB, NT>>>(in_features, tensor_rhats, dist_pairs, int_weights,
                        selfint_w, selfint_b, mixing_weights, gn_weight,
                        gn_bias, sens_mu, sens_sigma, pair_first, pair_second,
                        out);
}

// round 9
// speedup vs baseline: 1.1050x; 1.1045x over previous
#include <cuda_runtime.h>
#include <cuda_fp16.h>
#include <cstdint>

#define N_ATOMS 8000
#define N_PAIRS 80000
#define NF 32
#define GN_EPS 1e-5f

#define NB 500            // 4 CTAs/SM: 500 <= 592 capacity, all resident
#define NT 256
#define NWARPS (NB * 8)   // 4000 warps -> exactly 2 atoms per warp

// Scratch (device globals: no allocation allowed)
// A-table fp16 packed: A2[a*256 + q*32 + o] = half2( A[a,2q,o], A[a,2q+1,o] )
__device__ __align__(16) uint32_t g_A2[(size_t)N_ATOMS * 256];
// transposed fp16 weights: WT2[f*256 + q*32 + o] = half2(W[2q,o,f], W[2q+1,o,f])
__device__ __align__(16) uint32_t g_WT2[32 * 256];
// sense table fp32: sense[p*16 + d] = cut(d_p) * exp(...)
__device__ __align__(16) float g_sense[(size_t)N_PAIRS * 16];
__device__ __align__(16) float g_self[(size_t)N_ATOMS * NF];
__device__ int g_seg[N_ATOMS + 1];

// Grid barrier state: monotonic across launches (deterministic, no reset).
__device__ unsigned long long g_arrive = 0;
__device__ volatile unsigned long long g_release = 0;

__device__ __forceinline__ void grid_barrier() {
    __syncthreads();
    if (threadIdx.x == 0) {
        __threadfence();
        unsigned long long t = atomicAdd(&g_arrive, 1ULL) + 1ULL;
        unsigned long long target = ((t + NB - 1) / NB) * NB;
        if (t == target) {
            g_release = target;
        } else {
            // fixed short sleep: backoff oversleeps past release and adds
            // its max quantum straight onto the critical path (R6-R8 lesson)
            while (g_release < target) __nanosleep(64);
        }
        __threadfence();
    }
    __syncthreads();
}

__device__ __forceinline__ float warp_sum(float v) {
#pragma unroll
    for (int off = 16; off; off >>= 1)
        v += __shfl_xor_sync(0xffffffffu, v, off);
    return v;
}

__device__ __forceinline__ void loadA(uint32_t A[8], int j, int lane) {
    const uint32_t* base = g_A2 + (size_t)j * 256 + lane;
#pragma unroll
    for (int q = 0; q < 8; ++q) A[q] = __ldg(base + q * 32);
}

__global__ void __launch_bounds__(NT, 4) k_fused(
    const float* __restrict__ feat,     // (N,32)
    const float* __restrict__ rhats,    // (P,4)
    const float* __restrict__ dist,     // (P,)
    const float* __restrict__ Wint,     // (16,32,32) d,o,f
    const float* __restrict__ sw,       // (32,32) o,f
    const float* __restrict__ sb,       // (32,)
    const float* __restrict__ mw,       // (64,32)
    const float* __restrict__ gnw,      // (64,)
    const float* __restrict__ gnb,      // (64,)
    const float* __restrict__ mu,       // (16,)
    const float* __restrict__ sg,       // (16,)
    const int*   __restrict__ pf,       // (P,)  sorted
    const int*   __restrict__ psec,     // (P,)
    float* __restrict__ out)            // (N,32)
{
    __shared__ __align__(16) float swT[NF * NF];   // transposed selfint weights
    __shared__ __align__(16) float fsh[4 * NF];    // feat staging for A3 tiles

    const int tid  = threadIdx.x;
    const int bid  = blockIdx.x;
    const int lane = tid & 31;
    const int wid  = tid >> 5;
    const int gtid  = bid * NT + tid;
    const int gwarp = bid * 8 + wid;

    // per-lane sensitivity constants (d = lane & 15)
    const float mu_l  = mu[lane & 15];
    const float isg_l = 1.0f / sg[lane & 15];

    // ============================ PHASE A0 ==================================
    // A0a: segment starts via scatter on sorted pair_first
    for (int p = gtid; p < N_PAIRS; p += NB * NT) {
        int cur  = pf[p];
        int prev = (p == 0) ? -1 : pf[p - 1];
        for (int a = prev + 1; a <= cur; ++a) g_seg[a] = p;
        if (p == N_PAIRS - 1)
            for (int a = cur + 1; a <= N_ATOMS; ++a) g_seg[a] = N_PAIRS;
    }

    // A0b: sense table, warp-cooperative. lane = h*16 + d handles pair pb+h.
    // Store addr = (pb+h)*16 + d = pb*16 + lane -> one 128B wavefront / 2 pairs.
    {
        const int h = lane >> 4;                    // which of the 2 pairs
        for (int pb = gwarp * 2; pb < N_PAIRS; pb += NWARPS * 2) {
            const float dd = dist[pb + h];
            const float invd = 1.0f / dd;
            float cut = 0.f;
            if (dd < 6.5f) {
                float cc = cospif(dd * (0.5f / 6.5f));
                cut = cc * cc;
            }
            float t = (invd - mu_l) * isg_l;
            g_sense[(size_t)pb * 16 + lane] = cut * __expf(-0.5f * t * t);
        }
    }

    // A0c: one block builds the transposed fp16 weight table
    if (bid == NB - 1) {
        for (int idx = tid; idx < 32 * 256; idx += NT) {
            int f = idx >> 8, rem = idx & 255;
            int q = rem >> 5, o = rem & 31;
            float a = Wint[(2 * q) * (NF * NF) + o * NF + f];
            float b = Wint[(2 * q + 1) * (NF * NF) + o * NF + f];
            __half2 h2 = __floats2half2_rn(a, b);
            g_WT2[idx] = *reinterpret_cast<uint32_t*>(&h2);
        }
    }

    // A0d: self-interaction (fp32)
    for (int i = tid; i < NF * NF; i += NT) {
        int o = i >> 5, f = i & 31;
        swT[f * NF + o] = sw[i];
    }
    __syncthreads();
    for (int idx = gtid; idx < N_ATOMS * NF; idx += NB * NT) {
        int a = idx >> 5, o = idx & 31;
        float s = sb[o];
        const float* fr = feat + (size_t)a * NF;
#pragma unroll
        for (int f = 0; f < NF; ++f)
            s = fmaf(fr[f], swT[f * NF + o], s);
        g_self[idx] = s;
    }

    grid_barrier();

    // ============================ PHASE A3 ==================================
    // A-table GEMM; 4-atom tiles (8 accumulator regs), weights coalesced
    {
        const int c = wid * 32 + lane;
        const float4* fsh4 = (const float4*)fsh;
        for (int tile = bid; tile < N_ATOMS / 4; tile += NB) {
            const int a0 = tile * 4;
            __syncthreads();
            if (tid < 4 * NF) fsh[tid] = feat[(size_t)a0 * NF + tid];
            __syncthreads();
            float accA[4], accB[4];
#pragma unroll
            for (int k = 0; k < 4; ++k) { accA[k] = 0.f; accB[k] = 0.f; }
#pragma unroll
            for (int f4 = 0; f4 < 8; ++f4) {
                float2 wf[4];
#pragma unroll
                for (int t = 0; t < 4; ++t) {
                    uint32_t w2 = g_WT2[(4 * f4 + t) * 256 + c];
                    wf[t] = __half22float2(*reinterpret_cast<__half2*>(&w2));
                }
#pragma unroll
                for (int k = 0; k < 4; ++k) {
                    float4 v = fsh4[k * 8 + f4];
                    accA[k] = fmaf(v.x, wf[0].x, accA[k]);
                    accB[k] = fmaf(v.x, wf[0].y, accB[k]);
                    accA[k] = fmaf(v.y, wf[1].x, accA[k]);
                    accB[k] = fmaf(v.y, wf[1].y, accB[k]);
                    accA[k] = fmaf(v.z, wf[2].x, accA[k]);
                    accB[k] = fmaf(v.z, wf[2].y, accB[k]);
                    accA[k] = fmaf(v.w, wf[3].x, accA[k]);
                    accB[k] = fmaf(v.w, wf[3].y, accB[k]);
                }
            }
#pragma unroll
            for (int k = 0; k < 4; ++k) {
                __half2 h2 = __floats2half2_rn(accA[k], accB[k]);
                g_A2[(size_t)(a0 + k) * 256 + c] =
                    *reinterpret_cast<uint32_t*>(&h2);
            }
        }
    }

    grid_barrier();

    // ============================ PHASE B ===================================
    // static warp-per-atom, exactly 2 atoms per warp (perfect balance)
    for (int a = gwarp; a < N_ATOMS; a += NWARPS) {
        const int p0 = g_seg[a];
        const int n  = g_seg[a + 1] - p0;

        float acc0 = 0.f, acc1 = 0.f, acc2 = 0.f, acc3 = 0.f;

        auto process_pair = [&](const uint32_t (&B)[8], int p) {
            const float4* sp = (const float4*)(g_sense + 16 * (size_t)p);
            const float4 rh = *(const float4*)(rhats + 4 * (size_t)p);
            float dA = 0.f, dB = 0.f;
#pragma unroll
            for (int g = 0; g < 4; ++g) {
                float4 s = sp[g];
                float2 a0v = __half22float2(*(const __half2*)(&B[2 * g]));
                float2 a1v = __half22float2(*(const __half2*)(&B[2 * g + 1]));
                dA = fmaf(s.x, a0v.x, dA);
                dB = fmaf(s.y, a0v.y, dB);
                dA = fmaf(s.z, a1v.x, dA);
                dB = fmaf(s.w, a1v.y, dB);
            }
            const float wgt = dA + dB;
            acc0 = fmaf(rh.x, wgt, acc0);
            acc1 = fmaf(rh.y, wgt, acc1);
            acc2 = fmaf(rh.z, wgt, acc2);
            acc3 = fmaf(rh.w, wgt, acc3);
        };

        if (n > 0) {
            uint32_t b0[8], b1[8];
            loadA(b0, psec[p0], lane);
            if (n > 1) loadA(b1, psec[p0 + 1], lane);
            int i = 0;
            for (;;) {
                process_pair(b0, p0 + i);
                if (i + 2 < n) loadA(b0, psec[p0 + i + 2], lane);
                if (++i >= n) break;
                process_pair(b1, p0 + i);
                if (i + 2 < n) loadA(b1, psec[p0 + i + 2], lane);
                if (++i >= n) break;
            }
        }

        // invariants
        const float inv0 = acc0;
        const float inv1 = acc1 * acc1 + acc2 * acc2 + acc3 * acc3;

        // GroupNorm over 32 lanes per group
        const float m0 = warp_sum(inv0) * (1.f / 32.f);
        const float m1 = warp_sum(inv1) * (1.f / 32.f);
        const float c0 = inv0 - m0;
        const float c1 = inv1 - m1;
        const float v0s = warp_sum(c0 * c0) * (1.f / 32.f);
        const float v1s = warp_sum(c1 * c1) * (1.f / 32.f);
        float xn0 = c0 * rsqrtf(v0s + GN_EPS);
        float xn1 = c1 * rsqrtf(v1s + GN_EPS);
        xn0 = fmaf(xn0, gnw[lane], gnb[lane]);
        xn1 = fmaf(xn1, gnw[32 + lane], gnb[32 + lane]);

        // mixing + self
        float oa = g_self[(size_t)a * NF + lane];
        float ob = 0.f;
#pragma unroll
        for (int oin = 0; oin < 32; ++oin) {
            const float n0 = __shfl_sync(0xffffffffu, xn0, oin);
            const float n1 = __shfl_sync(0xffffffffu, xn1, oin);
            oa = fmaf(n0, mw[(oin * 2 + 0) * NF + lane], oa);
            ob = fmaf(n1, mw[(oin * 2 + 1) * NF + lane], ob);
        }
        out[(size_t)a * NF + lane] = oa + ob;
    }
}

// ---------------------------------------------------------------------------
extern "C" void kernel_launch(void* const* d_in, const int* in_sizes, int n_in,
                              void* d_out, int out_size) {
    const float* in_features = (const float*)d_in[0];
    const float* tensor_rhats = (const float*)d_in[1];
    const float* dist_pairs = (const float*)d_in[2];
    const float* int_weights = (const float*)d_in[3];
    const float* selfint_w = (const float*)d_in[4];
    const float* selfint_b = (const float*)d_in[5];
    const float* mixing_weights = (const float*)d_in[6];
    const float* gn_weight = (const float*)d_in[7];
    const float* gn_bias = (const float*)d_in[8];
    const float* sens_mu = (const float*)d_in[9];
    const float* sens_sigma = (const float*)d_in[10];
    const int* pair_first = (const int*)d_in[11];
    const int* pair_second = (const int*)d_in[12];
    float* out = (float*)d_out;

    k_fused<<<NB, NT>>>(in_features, tensor_rhats, dist_pairs, int_weights,
                        selfint_w, selfint_b, mixing_weights, gn_weight,
                        gn_bias, sens_mu, sens_sigma, pair_first, pair_second,
                        out);
}